// round 8
// baseline (speedup 1.0000x reference)
#include <cuda_runtime.h>

#define G        64
#define IMGSZ    512
#define NTHREADS 1024

#define EDGE_SCALE (1.0f / 0.875f)   // all patch-edge wsums are 7/8

__device__ __forceinline__ float ldimg(const float* __restrict__ img, int gy, int gx) {
    if ((unsigned)gy < IMGSZ && (unsigned)gx < IMGSZ)
        return __ldg(img + gy * IMGSZ + gx);
    return 0.0f;
}

// ======================= S = 4 (img4 -> window 2) =======================
// Vertical-first separable filter. Weights [1,3,5,7,7,5,3,1]/32.
// Chunk m = rows [4m-2, 4m+2): s_m = dot([1,3,5,7]/32), t_m = dot([7,5,3,1]/32),
// out_y = s_y + t_{y+1}. Rows outside patch/image load as 0; outputs y==0/63
// get *EDGE_SCALE (excluded-tap renorm).
// 1024 threads: j = tid&255 (patch column), h = tid>>8 (row quarter, 4 outputs,
// 5 chunks = 20 fully-unrolled independent loads).
// tmp layout: [16][264]; column j at offset j+2, pads zeroed, so horizontal
// chunk i is the aligned float4 at index i (row = 66 float4s).
__device__ void ds4_slice(const float* __restrict__ img, float* __restrict__ o,
                          int by, int bx, int y0, float* __restrict__ tmp) {
    constexpr int RP = 264;
    const int tid = threadIdx.x;

    if (tid < 16) {                 // zero the 4 pad cells of each row
        float* rp = tmp + tid * RP;
        rp[0] = 0.f; rp[1] = 0.f; rp[258] = 0.f; rp[259] = 0.f;
    }

    // ---- phase 1: vertical; 4 threads per column, 4 output rows each ----
    {
        const int j   = tid & 255;
        const int h   = tid >> 8;          // 0..3
        const int ylo = y0 + 4 * h;
        const int gx  = bx + j;
        if ((unsigned)gx >= (unsigned)IMGSZ) {
#pragma unroll
            for (int yy = 0; yy < 4; yy++) tmp[(4 * h + yy) * RP + 2 + j] = 0.f;
        } else {
            const float* colp = img + gx;
            const int rlo = 4 * ylo - 2;
            const int rhi = 4 * (ylo + 4) + 1;
            const bool allok = (rlo >= 0) && (rhi < 256) &&
                               (by + rlo >= 0) && (by + rhi < IMGSZ);
            float sp = 0.f;
            if (allok) {
                const float* p = colp + (size_t)(by + rlo) * IMGSZ;
#pragma unroll
                for (int cm = 0; cm <= 4; cm++) {
                    float v0 = __ldg(p + (4 * cm + 0) * IMGSZ);
                    float v1 = __ldg(p + (4 * cm + 1) * IMGSZ);
                    float v2 = __ldg(p + (4 * cm + 2) * IMGSZ);
                    float v3 = __ldg(p + (4 * cm + 3) * IMGSZ);
                    float s = fmaf(7.f/32, v3, fmaf(5.f/32, v2, fmaf(3.f/32, v1, (1.f/32)*v0)));
                    float t = fmaf(1.f/32, v3, fmaf(3.f/32, v2, fmaf(5.f/32, v1, (7.f/32)*v0)));
                    if (cm > 0) {
                        int y = ylo + cm - 1;
                        float raw = sp + t;
                        if (y == 0 || y == 63) raw *= EDGE_SCALE;
                        tmp[(4 * h + cm - 1) * RP + 2 + j] = raw;
                    }
                    sp = s;
                }
            } else {
#pragma unroll
                for (int cm = 0; cm <= 4; cm++) {
                    int rbase = 4 * (ylo + cm) - 2;
                    float v[4];
#pragma unroll
                    for (int k = 0; k < 4; k++) {
                        int r  = rbase + k;
                        int gy = by + r;
                        v[k] = ((unsigned)r < 256u && (unsigned)gy < (unsigned)IMGSZ)
                               ? __ldg(colp + (size_t)gy * IMGSZ) : 0.f;
                    }
                    float s = fmaf(7.f/32, v[3], fmaf(5.f/32, v[2], fmaf(3.f/32, v[1], (1.f/32)*v[0])));
                    float t = fmaf(1.f/32, v[3], fmaf(3.f/32, v[2], fmaf(5.f/32, v[1], (7.f/32)*v[0])));
                    if (cm > 0) {
                        int y = ylo + cm - 1;
                        float raw = sp + t;
                        if (y == 0 || y == 63) raw *= EDGE_SCALE;
                        tmp[(4 * h + cm - 1) * RP + 2 + j] = raw;
                    }
                    sp = s;
                }
            }
        }
    }
    __syncthreads();

    // ---- phase 2: horizontal from smem, aligned float4 chunks ----
    const float4* t4 = (const float4*)tmp;   // row stride 66 float4s
    for (int idx = tid; idx < 16 * G; idx += NTHREADS) {
        int yy = idx >> 6, i = idx & 63;
        float4 a = t4[yy * 66 + i];
        float4 b = t4[yy * 66 + i + 1];
        float acc = (1.f/32)*a.x + (3.f/32)*a.y + (5.f/32)*a.z + (7.f/32)*a.w
                  + (7.f/32)*b.x + (5.f/32)*b.y + (3.f/32)*b.z + (1.f/32)*b.w;
        if (i == 0 || i == 63) acc *= EDGE_SCALE;
        o[(y0 + yy) * G + i] = acc;
    }
}

// ======================= S = 2 (img2 -> window 1) =======================
// Weights [1,3,3,1]/8. Chunk m = rows {2m-1, 2m}: s=[1,3]/8, t=[3,1]/8.
// 32 output rows per slice; 1024 threads: j = tid&127 (column), h = tid>>7
// (eighth: 4 output rows, 5 chunks = 10 fully-unrolled loads).
// tmp: [32][132], col j at offset j+1, pads 0, so horizontal chunk i is the
// aligned float2 at index i (row = 66 float2s).
__device__ void ds2_slice(const float* __restrict__ img, float* __restrict__ o,
                          int by, int bx, int y0, float* __restrict__ tmp) {
    constexpr int RP = 132;
    const int tid = threadIdx.x;

    if (tid < 32) {                  // zero pad cells
        float* rp = tmp + tid * RP;
        rp[0] = 0.f; rp[129] = 0.f;
    }

    // ---- phase 1: vertical; 8 threads per column, 4 output rows each ----
    {
        const int j   = tid & 127;
        const int h   = tid >> 7;            // 0..7
        const int ylo = y0 + 4 * h;
        const int gx  = bx + j;
        if ((unsigned)gx >= (unsigned)IMGSZ) {
#pragma unroll
            for (int yy = 0; yy < 4; yy++) tmp[(4 * h + yy) * RP + 1 + j] = 0.f;
        } else {
            const float* colp = img + gx;
            const int rlo = 2 * ylo - 1;
            const int rhi = 2 * (ylo + 4);
            const bool allok = (rlo >= 0) && (rhi < 128) &&
                               (by + rlo >= 0) && (by + rhi < IMGSZ);
            float sp = 0.f;
            if (allok) {
                const float* p = colp + (size_t)(by + rlo) * IMGSZ;
#pragma unroll
                for (int cm = 0; cm <= 4; cm++) {
                    float v0 = __ldg(p + (2 * cm + 0) * IMGSZ);
                    float v1 = __ldg(p + (2 * cm + 1) * IMGSZ);
                    float s = fmaf(3.f/8, v1, (1.f/8)*v0);
                    float t = fmaf(1.f/8, v1, (3.f/8)*v0);
                    if (cm > 0) {
                        int y = ylo + cm - 1;
                        float raw = sp + t;
                        if (y == 0 || y == 63) raw *= EDGE_SCALE;
                        tmp[(4 * h + cm - 1) * RP + 1 + j] = raw;
                    }
                    sp = s;
                }
            } else {
#pragma unroll
                for (int cm = 0; cm <= 4; cm++) {
                    int rbase = 2 * (ylo + cm) - 1;
                    float v[2];
#pragma unroll
                    for (int k = 0; k < 2; k++) {
                        int r  = rbase + k;
                        int gy = by + r;
                        v[k] = ((unsigned)r < 128u && (unsigned)gy < (unsigned)IMGSZ)
                               ? __ldg(colp + (size_t)gy * IMGSZ) : 0.f;
                    }
                    float s = fmaf(3.f/8, v[1], (1.f/8)*v[0]);
                    float t = fmaf(1.f/8, v[1], (3.f/8)*v[0]);
                    if (cm > 0) {
                        int y = ylo + cm - 1;
                        float raw = sp + t;
                        if (y == 0 || y == 63) raw *= EDGE_SCALE;
                        tmp[(4 * h + cm - 1) * RP + 1 + j] = raw;
                    }
                    sp = s;
                }
            }
        }
    }
    __syncthreads();

    // ---- phase 2: horizontal from smem, aligned float2 chunks ----
    const float2* t2 = (const float2*)tmp;   // row stride 66 float2s
    for (int idx = tid; idx < 32 * G; idx += NTHREADS) {
        int yy = idx >> 6, i = idx & 63;
        float2 a = t2[yy * 66 + i];
        float2 b = t2[yy * 66 + i + 1];
        float acc = (1.f/8)*a.x + (3.f/8)*a.y + (3.f/8)*b.x + (1.f/8)*b.y;
        if (i == 0 || i == 63) acc *= EDGE_SCALE;
        o[(y0 + yy) * G + i] = acc;
    }
}

// Grid (1344 blocks), heavy work first:
//   [0, 768)     : S=4, 4 slices x 16 rows per (b,c)
//   [768, 1152)  : S=2, 2 slices x 32 rows per (b,c)
//   [1152, 1344) : direct 64x64 zero-padded crop of img0
__global__ __launch_bounds__(NTHREADS, 2)
void glimpse_kernel(const float* __restrict__ img0,
                    const float* __restrict__ img2,
                    const float* __restrict__ img4,
                    const float* __restrict__ loc,
                    float* __restrict__ out) {
    extern __shared__ float tmp[];

    int blk = blockIdx.x;
    int sel, bc, slice;
    if (blk < 768)       { sel = 0; bc = blk >> 2;          slice = blk & 3; }
    else if (blk < 1152) { sel = 1; bc = (blk - 768) >> 1;  slice = (blk - 768) & 1; }
    else                 { sel = 2; bc = blk - 1152;        slice = 0; }
    int b = bc / 3;
    int c = bc - b * 3;

    // start index, matching jnp: trunc(0.5f * ((loc + 1.0f) * 511.0f))
    float lx = loc[2 * b + 0];
    float ly = loc[2 * b + 1];
    int sx = (int)(0.5f * ((lx + 1.0f) * 511.0f));
    int sy = (int)(0.5f * ((ly + 1.0f) * 511.0f));

    if (sel == 0) {
        const float* img = img4 + (size_t)(b * 3 + c) * IMGSZ * IMGSZ;
        float* o = out + (size_t)((b * 3 + 2) * 3 + c) * G * G;
        ds4_slice(img, o, sy - 128, sx - 128, slice * 16, tmp);
    } else if (sel == 1) {
        const float* img = img2 + (size_t)(b * 3 + c) * IMGSZ * IMGSZ;
        float* o = out + (size_t)((b * 3 + 1) * 3 + c) * G * G;
        ds2_slice(img, o, sy - 64, sx - 64, slice * 32, tmp);
    } else {
        const float* img = img0 + (size_t)(b * 3 + c) * IMGSZ * IMGSZ;
        float* o = out + (size_t)((b * 3 + 0) * 3 + c) * G * G;
        int by = sy - G / 2, bx = sx - G / 2;
        for (int idx = threadIdx.x; idx < G * G; idx += NTHREADS) {
            int y = idx >> 6, x = idx & 63;
            o[idx] = ldimg(img, by + y, bx + x);
        }
    }
}

extern "C" void kernel_launch(void* const* d_in, const int* in_sizes, int n_in,
                              void* d_out, int out_size) {
    const float* img0 = (const float*)d_in[0];
    const float* img2 = (const float*)d_in[1];
    const float* img4 = (const float*)d_in[2];
    const float* loc  = (const float*)d_in[3];
    float* out = (float*)d_out;

    const size_t smem = 16896;   // max(16*264, 32*132) * 4 bytes
    cudaFuncSetAttribute(glimpse_kernel,
                         cudaFuncAttributeMaxDynamicSharedMemorySize, (int)smem);
    glimpse_kernel<<<1344, NTHREADS, smem>>>(img0, img2, img4, loc, out);
}